// round 4
// baseline (speedup 1.0000x reference)
#include <cuda_runtime.h>
#include <cstdint>

#define N_NODES   1000000
#define D_IN      128
#define H1DIM     64
#define D2        256     // 2 * GRAPH_STATE_DIM
#define GS        128     // GRAPH_STATE_DIM
#define NG        4096

// Scratch accumulator for segment sums (device global: allocation-free).
__device__ float g_graph_states[NG * GS];

// ---------- packed f32x2 helpers (Blackwell FFMA2 path) ----------
__device__ __forceinline__ unsigned long long pack2f(float x, float y) {
    unsigned long long r;
    asm("mov.b64 %0, {%1,%2};" : "=l"(r) : "f"(x), "f"(y));
    return r;
}
__device__ __forceinline__ void unpack2f(unsigned long long p, float &x, float &y) {
    asm("mov.b64 {%0,%1}, %2;" : "=f"(x), "=f"(y) : "l"(p));
}
__device__ __forceinline__ void ffma2(unsigned long long &d, unsigned long long a, unsigned long long b) {
    asm("fma.rn.f32x2 %0, %1, %2, %0;" : "+l"(d) : "l"(a), "l"(b));
}

// ---------- kernel 0: zero the graph-state accumulator ----------
__global__ void zero_states_kernel() {
    int i = blockIdx.x * blockDim.x + threadIdx.x;   // 512*256 = 131072 = NG*GS/4
    float4 z = make_float4(0.f, 0.f, 0.f, 0.f);
    ((float4*)g_graph_states)[i] = z;
}

// ---------- kernel 1: fused MLP1 + gate + segment-sum (red.v4) ----------
__global__ __launch_bounds__(256, 1) void mlp1_gate_scatter_kernel(
    const float* __restrict__ X,      // [N_NODES, D_IN]
    const int*   __restrict__ gidx,   // [N_NODES]
    const float* __restrict__ W1,     // [D_IN, H1DIM]
    const float* __restrict__ b1,     // [H1DIM]
    const float* __restrict__ W2,     // [H1DIM, D2]
    const float* __restrict__ b2)     // [D2]
{
    extern __shared__ float smem[];
    float* W1s = smem;                       // 8192 floats
    float* W2s = W1s + D_IN * H1DIM;         // 16384 floats
    float* h1s = W2s + H1DIM * D2;           // 64 * 256 = 16384 floats, layout [k][tid]
    float* b1s = h1s + H1DIM * 256;          // 64
    float* b2s = b1s + 64;                   // 256

    const int tid = threadIdx.x;

    // Stage weights/biases in shared (broadcast-read later, conflict-free).
    {
        float4*       d4 = (float4*)W1s;
        const float4* s4 = (const float4*)W1;
        for (int i = tid; i < (D_IN * H1DIM) / 4; i += 256) d4[i] = s4[i];
        d4 = (float4*)W2s; s4 = (const float4*)W2;
        for (int i = tid; i < (H1DIM * D2) / 4; i += 256) d4[i] = s4[i];
        if (tid < 64)  b1s[tid] = b1[tid];
        b2s[tid] = b2[tid];
    }
    __syncthreads();

    const int nTiles = (N_NODES + 255) / 256;
    float* const my = &h1s[tid];   // stride-256 column, conflict-free

    #pragma unroll 1
    for (int tile = blockIdx.x; tile < nTiles; tile += gridDim.x) {
        const int n = tile * 256 + tid;
        if (n >= N_NODES) continue;

        // ---------- layer 1: h1 = relu(x @ W1 + b1), packed f32x2 ----------
        unsigned long long h1p[H1DIM / 2];
        #pragma unroll
        for (int q = 0; q < H1DIM / 2; ++q)
            h1p[q] = *(const unsigned long long*)(&b1s[2 * q]);

        const float4* xrow = (const float4*)(X + (size_t)n * D_IN);
        #pragma unroll 1
        for (int k4 = 0; k4 < D_IN / 4; ++k4) {
            const float4 xv = __ldg(&xrow[k4]);
            #pragma unroll
            for (int kk = 0; kk < 4; ++kk) {
                const float xk = (kk == 0) ? xv.x : (kk == 1) ? xv.y : (kk == 2) ? xv.z : xv.w;
                const unsigned long long xp = pack2f(xk, xk);
                const ulonglong2* wr = (const ulonglong2*)(&W1s[(k4 * 4 + kk) * H1DIM]);
                #pragma unroll
                for (int q = 0; q < 16; ++q) {
                    ulonglong2 w = wr[q];           // LDS.128 broadcast
                    ffma2(h1p[2 * q],     xp, w.x);
                    ffma2(h1p[2 * q + 1], xp, w.y);
                }
            }
        }
        // relu + stash to shared for dynamic indexing in layer 2
        #pragma unroll
        for (int q = 0; q < H1DIM / 2; ++q) {
            float a, b; unpack2f(h1p[q], a, b);
            my[(2 * q)     * 256] = fmaxf(a, 0.f);
            my[(2 * q + 1) * 256] = fmaxf(b, 0.f);
        }

        float* const gsout = g_graph_states + (size_t)__ldg(&gidx[n]) * GS;

        // ---------- layer 2 in 4 chunks of (32 gate cols + 32 value cols) ----------
        #pragma unroll 1
        for (int c = 0; c < 4; ++c) {
            unsigned long long ag[16], av[16];
            #pragma unroll
            for (int q = 0; q < 16; ++q) {
                ag[q] = *(const unsigned long long*)(&b2s[c * 32 + 2 * q]);
                av[q] = *(const unsigned long long*)(&b2s[GS + c * 32 + 2 * q]);
            }
            #pragma unroll 2
            for (int k = 0; k < H1DIM; ++k) {
                const float hk = my[k * 256];
                const unsigned long long hp = pack2f(hk, hk);
                const ulonglong2* wg = (const ulonglong2*)(&W2s[k * D2 + c * 32]);
                const ulonglong2* wv = (const ulonglong2*)(&W2s[k * D2 + GS + c * 32]);
                #pragma unroll
                for (int q = 0; q < 8; ++q) {
                    ulonglong2 a = wg[q];
                    ffma2(ag[2 * q],     hp, a.x);
                    ffma2(ag[2 * q + 1], hp, a.y);
                    ulonglong2 b = wv[q];
                    ffma2(av[2 * q],     hp, b.x);
                    ffma2(av[2 * q + 1], hp, b.y);
                }
            }
            // gate: gated = value * sigmoid(gate)
            float gg[32];
            #pragma unroll
            for (int q = 0; q < 16; ++q) {
                float g0, g1, v0, v1;
                unpack2f(ag[q], g0, g1);
                unpack2f(av[q], v0, v1);
                gg[2 * q]     = __fdividef(v0, 1.f + __expf(-g0));
                gg[2 * q + 1] = __fdividef(v1, 1.f + __expf(-g1));
            }
            // vectorized reduction into graph accumulator
            #pragma unroll
            for (int i = 0; i < 8; ++i) {
                asm volatile("red.global.add.v4.f32 [%0], {%1,%2,%3,%4};"
                             :: "l"(gsout + c * 32 + 4 * i),
                                "f"(gg[4 * i]), "f"(gg[4 * i + 1]),
                                "f"(gg[4 * i + 2]), "f"(gg[4 * i + 3])
                             : "memory");
            }
        }
    }
}

// ---------- kernel 2: MLP2 over 4096 graphs ----------
__global__ __launch_bounds__(128) void mlp2_kernel(
    const float* __restrict__ W3,   // [GS, 32]
    const float* __restrict__ b3,   // [32]
    const float* __restrict__ W4,   // [32, 16]
    const float* __restrict__ b4,   // [16]
    float* __restrict__ out)        // [NG, 16]
{
    __shared__ float W3s[GS * 32];
    __shared__ float W4s[32 * 16];
    __shared__ float b3s[32];
    __shared__ float b4s[16];

    const int tid = threadIdx.x;
    for (int i = tid; i < (GS * 32) / 4; i += 128) ((float4*)W3s)[i] = ((const float4*)W3)[i];
    for (int i = tid; i < (32 * 16) / 4; i += 128) ((float4*)W4s)[i] = ((const float4*)W4)[i];
    if (tid < 32) b3s[tid] = b3[tid];
    if (tid < 16) b4s[tid] = b4[tid];
    __syncthreads();

    const int g = blockIdx.x * 128 + tid;

    float h3[32];
    #pragma unroll
    for (int j = 0; j < 32; ++j) h3[j] = b3s[j];

    const float4* gr = (const float4*)(g_graph_states + (size_t)g * GS);
    #pragma unroll 1
    for (int k4 = 0; k4 < GS / 4; ++k4) {
        const float4 gv = gr[k4];
        #pragma unroll
        for (int kk = 0; kk < 4; ++kk) {
            const float gk = (kk == 0) ? gv.x : (kk == 1) ? gv.y : (kk == 2) ? gv.z : gv.w;
            const float* w = &W3s[(k4 * 4 + kk) * 32];
            #pragma unroll
            for (int j = 0; j < 32; ++j) h3[j] += gk * w[j];
        }
    }

    float o[16];
    #pragma unroll
    for (int j = 0; j < 16; ++j) o[j] = b4s[j];
    #pragma unroll
    for (int k = 0; k < 32; ++k) {
        const float hk = fmaxf(h3[k], 0.f);
        #pragma unroll
        for (int j = 0; j < 16; ++j) o[j] += hk * W4s[k * 16 + j];
    }

    float4* op = (float4*)(out + (size_t)g * 16);
    op[0] = make_float4(o[0],  o[1],  o[2],  o[3]);
    op[1] = make_float4(o[4],  o[5],  o[6],  o[7]);
    op[2] = make_float4(o[8],  o[9],  o[10], o[11]);
    op[3] = make_float4(o[12], o[13], o[14], o[15]);
}

extern "C" void kernel_launch(void* const* d_in, const int* in_sizes, int n_in,
                              void* d_out, int out_size)
{
    const float* X  = (const float*)d_in[0];
    const int*   gi = (const int*)  d_in[1];
    const float* W1 = (const float*)d_in[2];
    const float* b1 = (const float*)d_in[3];
    const float* W2 = (const float*)d_in[4];
    const float* b2 = (const float*)d_in[5];
    const float* W3 = (const float*)d_in[6];
    const float* b3 = (const float*)d_in[7];
    const float* W4 = (const float*)d_in[8];
    const float* b4 = (const float*)d_in[9];
    float* out = (float*)d_out;

    const int smem_bytes = (D_IN * H1DIM + H1DIM * D2 + H1DIM * 256 + 64 + 256) * 4; // 165120
    cudaFuncSetAttribute(mlp1_gate_scatter_kernel,
                         cudaFuncAttributeMaxDynamicSharedMemorySize, smem_bytes);

    zero_states_kernel<<<512, 256>>>();
    mlp1_gate_scatter_kernel<<<304, 256, smem_bytes>>>(X, gi, W1, b1, W2, b2);
    mlp2_kernel<<<NG / 128, 128>>>(W3, b3, W4, b4, out);
}

// round 6
// speedup vs baseline: 1.0248x; 1.0248x over previous
#include <cuda_runtime.h>
#include <cstdint>

#define N_NODES   1000000
#define D_IN      128
#define H1DIM     64
#define D2        256     // 2 * GRAPH_STATE_DIM
#define GS        128     // GRAPH_STATE_DIM
#define NG        4096

// Scratch accumulator for segment sums (device global: allocation-free).
__device__ float g_graph_states[NG * GS];

// ---------- packed f32x2 helpers (Blackwell FFMA2 path) ----------
__device__ __forceinline__ unsigned long long pack2f(float x, float y) {
    unsigned long long r;
    asm("mov.b64 %0, {%1,%2};" : "=l"(r) : "f"(x), "f"(y));
    return r;
}
__device__ __forceinline__ void unpack2f(unsigned long long p, float &x, float &y) {
    asm("mov.b64 {%0,%1}, %2;" : "=f"(x), "=f"(y) : "l"(p));
}
__device__ __forceinline__ void ffma2(unsigned long long &d, unsigned long long a, unsigned long long b) {
    asm("fma.rn.f32x2 %0, %1, %2, %0;" : "+l"(d) : "l"(a), "l"(b));
}

// ---------- kernel 0: zero the graph-state accumulator ----------
__global__ void zero_states_kernel() {
    int i = blockIdx.x * blockDim.x + threadIdx.x;   // 512*256 = 131072 = NG*GS/4
    ((float4*)g_graph_states)[i] = make_float4(0.f, 0.f, 0.f, 0.f);
}

// Layer-1 partial: 16 k-values from a register batch of 4 float4.
__device__ __forceinline__ void l1_batch(const float4 xb[4], int k0,
                                         unsigned long long h1p[32],
                                         const float* __restrict__ W1s)
{
    #pragma unroll
    for (int j = 0; j < 4; ++j) {
        #pragma unroll
        for (int kk = 0; kk < 4; ++kk) {
            const float xk = (kk == 0) ? xb[j].x : (kk == 1) ? xb[j].y
                           : (kk == 2) ? xb[j].z : xb[j].w;
            const unsigned long long xp = pack2f(xk, xk);
            const ulonglong2* wr =
                (const ulonglong2*)(&W1s[(k0 + j * 4 + kk) * H1DIM]);
            #pragma unroll
            for (int q = 0; q < 16; ++q) {
                ulonglong2 w = wr[q];                // LDS.128 broadcast
                ffma2(h1p[2 * q],     xp, w.x);
                ffma2(h1p[2 * q + 1], xp, w.y);
            }
        }
    }
}

// ---------- kernel 1: fused MLP1 + gate + segment-sum (red.v4) ----------
// 2 CTAs/SM (97KB smem each), h1 register-resident, double-buffered X loads.
__global__ __launch_bounds__(256, 2) void mlp1_gate_scatter_kernel(
    const float* __restrict__ X,      // [N_NODES, D_IN]
    const int*   __restrict__ gidx,   // [N_NODES]
    const float* __restrict__ W1,     // [D_IN, H1DIM]
    const float* __restrict__ b1,     // [H1DIM]
    const float* __restrict__ W2,     // [H1DIM, D2]
    const float* __restrict__ b2)     // [D2]
{
    extern __shared__ float smem[];
    float* W1s = smem;                       // 8192 floats
    float* W2s = W1s + D_IN * H1DIM;         // 16384 floats
    float* b1s = W2s + H1DIM * D2;           // 64
    float* b2s = b1s + 64;                   // 256   (total 24896 floats = 99584 B)

    const int tid = threadIdx.x;

    // Stage weights/biases in shared (uniform broadcast reads later).
    {
        float4*       d4 = (float4*)W1s;
        const float4* s4 = (const float4*)W1;
        for (int i = tid; i < (D_IN * H1DIM) / 4; i += 256) d4[i] = s4[i];
        d4 = (float4*)W2s; s4 = (const float4*)W2;
        for (int i = tid; i < (H1DIM * D2) / 4; i += 256) d4[i] = s4[i];
        if (tid < 64)  b1s[tid] = b1[tid];
        b2s[tid] = b2[tid];
    }
    __syncthreads();

    const int nTiles = (N_NODES + 255) / 256;

    #pragma unroll 1
    for (int tile = blockIdx.x; tile < nTiles; tile += gridDim.x) {
        const int n = tile * 256 + tid;
        if (n >= N_NODES) continue;

        const int g = __ldg(&gidx[n]);       // issued early, used late

        // ---------- layer 1: h1 = relu(x @ W1 + b1), packed f32x2 ----------
        unsigned long long h1p[H1DIM / 2];
        #pragma unroll
        for (int q = 0; q < H1DIM / 2; ++q)
            h1p[q] = *(const unsigned long long*)(&b1s[2 * q]);

        const float4* xr = (const float4*)(X + (size_t)n * D_IN);  // 32 float4
        float4 xA[4], xB[4];
        #pragma unroll
        for (int j = 0; j < 4; ++j) xA[j] = __ldg(&xr[j]);         // batch 0

        #pragma unroll 1
        for (int bb = 0; bb < 4; ++bb) {     // two 16-k batches per iteration
            #pragma unroll
            for (int j = 0; j < 4; ++j) xB[j] = __ldg(&xr[(2 * bb + 1) * 4 + j]);
            l1_batch(xA, (2 * bb) * 16, h1p, W1s);
            if (bb < 3) {
                #pragma unroll
                for (int j = 0; j < 4; ++j) xA[j] = __ldg(&xr[(2 * bb + 2) * 4 + j]);
            }
            l1_batch(xB, (2 * bb + 1) * 16, h1p, W1s);
        }

        // relu -> register-resident h1 (static indexing only)
        float h1f[H1DIM];
        #pragma unroll
        for (int q = 0; q < H1DIM / 2; ++q) {
            float a, b; unpack2f(h1p[q], a, b);
            h1f[2 * q]     = fmaxf(a, 0.f);
            h1f[2 * q + 1] = fmaxf(b, 0.f);
        }

        float* const gsout = g_graph_states + (size_t)g * GS;

        // ---------- layer 2: 8 chunks of (16 gate + 16 value) columns ----------
        #pragma unroll 1
        for (int c = 0; c < 8; ++c) {
            unsigned long long ag[8], av[8];
            #pragma unroll
            for (int q = 0; q < 8; ++q) {
                ag[q] = *(const unsigned long long*)(&b2s[c * 16 + 2 * q]);
                av[q] = *(const unsigned long long*)(&b2s[GS + c * 16 + 2 * q]);
            }
            #pragma unroll
            for (int k = 0; k < H1DIM; ++k) {          // fully unrolled
                const unsigned long long hp = pack2f(h1f[k], h1f[k]);
                const ulonglong2* wg = (const ulonglong2*)(&W2s[k * D2 + c * 16]);
                const ulonglong2* wv = (const ulonglong2*)(&W2s[k * D2 + GS + c * 16]);
                #pragma unroll
                for (int q = 0; q < 4; ++q) {          // 4 x 16B = all 16 cols (fixed)
                    ulonglong2 a = wg[q];
                    ffma2(ag[2 * q],     hp, a.x);
                    ffma2(ag[2 * q + 1], hp, a.y);
                    ulonglong2 b = wv[q];
                    ffma2(av[2 * q],     hp, b.x);
                    ffma2(av[2 * q + 1], hp, b.y);
                }
            }
            // gated = value * sigmoid(gate)
            float gg[16];
            #pragma unroll
            for (int q = 0; q < 8; ++q) {
                float g0, g1, v0, v1;
                unpack2f(ag[q], g0, g1);
                unpack2f(av[q], v0, v1);
                gg[2 * q]     = __fdividef(v0, 1.f + __expf(-g0));
                gg[2 * q + 1] = __fdividef(v1, 1.f + __expf(-g1));
            }
            #pragma unroll
            for (int i = 0; i < 4; ++i) {
                asm volatile("red.global.add.v4.f32 [%0], {%1,%2,%3,%4};"
                             :: "l"(gsout + c * 16 + 4 * i),
                                "f"(gg[4 * i]), "f"(gg[4 * i + 1]),
                                "f"(gg[4 * i + 2]), "f"(gg[4 * i + 3])
                             : "memory");
            }
        }
    }
}

// ---------- kernel 2: MLP2 over 4096 graphs ----------
__global__ __launch_bounds__(128) void mlp2_kernel(
    const float* __restrict__ W3,   // [GS, 32]
    const float* __restrict__ b3,   // [32]
    const float* __restrict__ W4,   // [32, 16]
    const float* __restrict__ b4,   // [16]
    float* __restrict__ out)        // [NG, 16]
{
    __shared__ float W3s[GS * 32];
    __shared__ float W4s[32 * 16];
    __shared__ float b3s[32];
    __shared__ float b4s[16];

    const int tid = threadIdx.x;
    for (int i = tid; i < (GS * 32) / 4; i += 128) ((float4*)W3s)[i] = ((const float4*)W3)[i];
    for (int i = tid; i < (32 * 16) / 4; i += 128) ((float4*)W4s)[i] = ((const float4*)W4)[i];
    if (tid < 32) b3s[tid] = b3[tid];
    if (tid < 16) b4s[tid] = b4[tid];
    __syncthreads();

    const int g = blockIdx.x * 128 + tid;

    float h3[32];
    #pragma unroll
    for (int j = 0; j < 32; ++j) h3[j] = b3s[j];

    const float4* gr = (const float4*)(g_graph_states + (size_t)g * GS);
    #pragma unroll 1
    for (int k4 = 0; k4 < GS / 4; ++k4) {
        const float4 gv = gr[k4];
        #pragma unroll
        for (int kk = 0; kk < 4; ++kk) {
            const float gk = (kk == 0) ? gv.x : (kk == 1) ? gv.y : (kk == 2) ? gv.z : gv.w;
            const float* w = &W3s[(k4 * 4 + kk) * 32];
            #pragma unroll
            for (int j = 0; j < 32; ++j) h3[j] += gk * w[j];
        }
    }

    float o[16];
    #pragma unroll
    for (int j = 0; j < 16; ++j) o[j] = b4s[j];
    #pragma unroll
    for (int k = 0; k < 32; ++k) {
        const float hk = fmaxf(h3[k], 0.f);
        #pragma unroll
        for (int j = 0; j < 16; ++j) o[j] += hk * W4s[k * 16 + j];
    }

    float4* op = (float4*)(out + (size_t)g * 16);
    op[0] = make_float4(o[0],  o[1],  o[2],  o[3]);
    op[1] = make_float4(o[4],  o[5],  o[6],  o[7]);
    op[2] = make_float4(o[8],  o[9],  o[10], o[11]);
    op[3] = make_float4(o[12], o[13], o[14], o[15]);
}

extern "C" void kernel_launch(void* const* d_in, const int* in_sizes, int n_in,
                              void* d_out, int out_size)
{
    const float* X  = (const float*)d_in[0];
    const int*   gi = (const int*)  d_in[1];
    const float* W1 = (const float*)d_in[2];
    const float* b1 = (const float*)d_in[3];
    const float* W2 = (const float*)d_in[4];
    const float* b2 = (const float*)d_in[5];
    const float* W3 = (const float*)d_in[6];
    const float* b3 = (const float*)d_in[7];
    const float* W4 = (const float*)d_in[8];
    const float* b4 = (const float*)d_in[9];
    float* out = (float*)d_out;

    const int smem_bytes = (D_IN * H1DIM + H1DIM * D2 + 64 + 256) * 4; // 99584
    cudaFuncSetAttribute(mlp1_gate_scatter_kernel,
                         cudaFuncAttributeMaxDynamicSharedMemorySize, smem_bytes);

    zero_states_kernel<<<512, 256>>>();
    mlp1_gate_scatter_kernel<<<296, 256, smem_bytes>>>(X, gi, W1, b1, W2, b2);
    mlp2_kernel<<<NG / 128, 128>>>(W3, b3, W4, b4, out);
}

// round 8
// speedup vs baseline: 2.8376x; 2.7688x over previous
#include <cuda_runtime.h>
#include <cuda_bf16.h>
#include <cstdint>

#define N_NODES 1000000
#define D_IN    128
#define H1      64
#define D2C     256
#define GS      128
#define NG      4096
#define TILE_M  128
#define N_TILES ((N_NODES + TILE_M - 1) / TILE_M)   // 7813

__device__ float g_graph_states[NG * GS];
__device__ __align__(16) __nv_bfloat16 gW1h[H1 * D_IN];    // [n][k]
__device__ __align__(16) __nv_bfloat16 gW1l[H1 * D_IN];
__device__ __align__(16) __nv_bfloat16 gW2h[D2C * H1];     // [n][k]
__device__ __align__(16) __nv_bfloat16 gW2l[D2C * H1];

// ---------------- helpers ----------------
__device__ __forceinline__ uint32_t smem_u32(const void* p) {
    uint32_t a;
    asm("{ .reg .u64 t; cvta.to.shared.u64 t, %1; cvt.u32.u64 %0, t; }" : "=r"(a) : "l"(p));
    return a;
}
__device__ __forceinline__ void ldsm4(uint32_t* r, uint32_t addr) {
    asm volatile("ldmatrix.sync.aligned.m8n8.x4.shared.b16 {%0,%1,%2,%3}, [%4];"
                 : "=r"(r[0]), "=r"(r[1]), "=r"(r[2]), "=r"(r[3]) : "r"(addr));
}
__device__ __forceinline__ void hmma(float* d, const uint32_t* a, uint32_t b0, uint32_t b1) {
    asm volatile("mma.sync.aligned.m16n8k16.row.col.f32.bf16.bf16.f32 "
                 "{%0,%1,%2,%3}, {%4,%5,%6,%7}, {%8,%9}, {%0,%1,%2,%3};"
                 : "+f"(d[0]), "+f"(d[1]), "+f"(d[2]), "+f"(d[3])
                 : "r"(a[0]), "r"(a[1]), "r"(a[2]), "r"(a[3]), "r"(b0), "r"(b1));
}
// pack (f0,f1) -> bf16x2 (f0 low); returns hi-part; writes residual lo-part pack
__device__ __forceinline__ uint32_t cvt_hi(float f0, float f1) {
    uint32_t r;
    asm("cvt.rn.bf16x2.f32 %0, %1, %2;" : "=r"(r) : "f"(f1), "f"(f0));
    return r;
}
__device__ __forceinline__ uint32_t cvt_hilo(float f0, float f1, uint32_t& hi) {
    hi = cvt_hi(f0, f1);
    float h0 = __uint_as_float(hi << 16);
    float h1 = __uint_as_float(hi & 0xffff0000u);
    return cvt_hi(f0 - h0, f1 - h1);
}
__device__ __forceinline__ void red2(float* p, float x, float y) {
    asm volatile("red.global.add.v2.f32 [%0], {%1,%2};" :: "l"(p), "f"(x), "f"(y) : "memory");
}

// ---------------- prep: W transpose + hi/lo split ----------------
__global__ void prep_kernel(const float* __restrict__ W1, const float* __restrict__ W2) {
    int i = blockIdx.x * blockDim.x + threadIdx.x;
    if (i < H1 * D_IN) {
        int n = i >> 7, k = i & 127;
        float w = W1[k * H1 + n];
        __nv_bfloat16 h = __float2bfloat16(w);
        gW1h[i] = h;
        gW1l[i] = __float2bfloat16(w - __bfloat162float(h));
    }
    if (i < D2C * H1) {
        int n = i >> 6, k = i & 63;
        float w = W2[k * D2C + n];
        __nv_bfloat16 h = __float2bfloat16(w);
        gW2h[i] = h;
        gW2l[i] = __float2bfloat16(w - __bfloat162float(h));
    }
}

// ---------------- SMEM layout (bytes) ----------------
#define OF_XH  0          // 128 rows x 256B (swizzled, 16 chunks)
#define OF_XL  32768
#define OF_W1H 65536      // 64 rows x 256B
#define OF_W1L 81920
#define OF_W2H 98304      // 256 rows x 128B (8 chunks)
#define OF_W2L 131072
#define OF_B1  163840     // 64 f32
#define OF_B2  164096     // 256 f32
#define OF_GI  165120     // 128 int
#define SMEM_TOTAL 165664

// ---------------- fused HMMA kernel ----------------
__global__ __launch_bounds__(128, 1)
void mma_fused_kernel(const float* __restrict__ X, const int* __restrict__ gidx,
                      const float* __restrict__ b1, const float* __restrict__ b2,
                      int tile_begin, int tile_end)
{
    extern __shared__ char smem[];
    const uint32_t sb = smem_u32(smem);
    const int tid = threadIdx.x;
    const int L   = tid & 31;
    const int m0  = (tid >> 5) * 32;            // warp's 32 rows
    float* b1s = (float*)(smem + OF_B1);
    float* b2s = (float*)(smem + OF_B2);
    int*   sGI = (int*)(smem + OF_GI);

    // ---- stage weights (swizzled for ldmatrix) + biases ----
    for (int i = tid; i < H1 * 16; i += 128) {            // W1: 64 rows x 16 chunks
        int n = i >> 4, c = i & 15;
        uint32_t off = n * 256 + ((c ^ (n & 7)) << 4);
        *(uint4*)(smem + OF_W1H + off) = *(const uint4*)(gW1h + n * D_IN + c * 8);
        *(uint4*)(smem + OF_W1L + off) = *(const uint4*)(gW1l + n * D_IN + c * 8);
    }
    for (int i = tid; i < D2C * 8; i += 128) {            // W2: 256 rows x 8 chunks
        int n = i >> 3, c = i & 7;
        uint32_t off = n * 128 + ((c ^ (n & 7)) << 4);
        *(uint4*)(smem + OF_W2H + off) = *(const uint4*)(gW2h + n * H1 + c * 8);
        *(uint4*)(smem + OF_W2L + off) = *(const uint4*)(gW2l + n * H1 + c * 8);
    }
    if (tid < 64) b1s[tid] = b1[tid];
    for (int i = tid; i < 256; i += 128) b2s[i] = b2[i];
    __syncthreads();

    for (int tile = tile_begin + blockIdx.x; tile < tile_end; tile += gridDim.x) {
        // ---- phase A: X row -> hi/lo bf16 swizzled SMEM; stage gidx ----
        const int node = tile * TILE_M + tid;
        const bool valid = node < N_NODES;
        sGI[tid] = valid ? __ldg(&gidx[node]) : -1;
        const float4* xr = (const float4*)(X + (size_t)node * D_IN);
        #pragma unroll 4
        for (int c = 0; c < 16; ++c) {
            uint4 H = make_uint4(0, 0, 0, 0), Lo = make_uint4(0, 0, 0, 0);
            if (valid) {
                float4 a = __ldg(&xr[2 * c]), b = __ldg(&xr[2 * c + 1]);
                Lo.x = cvt_hilo(a.x, a.y, H.x);
                Lo.y = cvt_hilo(a.z, a.w, H.y);
                Lo.z = cvt_hilo(b.x, b.y, H.z);
                Lo.w = cvt_hilo(b.z, b.w, H.w);
            }
            uint32_t off = tid * 256 + ((c ^ (tid & 7)) << 4);
            *(uint4*)(smem + OF_XH + off) = H;
            *(uint4*)(smem + OF_XL + off) = Lo;
        }
        __syncthreads();

        // ---- layer 1: [128,128] @ W1^T[128,64], 3 split products ----
        float acc[2][8][4];
        #pragma unroll
        for (int mt = 0; mt < 2; ++mt)
            #pragma unroll
            for (int nt = 0; nt < 8; ++nt)
                #pragma unroll
                for (int j = 0; j < 4; ++j) acc[mt][nt][j] = 0.f;

        #pragma unroll 1
        for (int ks = 0; ks < 8; ++ks) {
            const int cc = ks * 2 + (L >> 4);
            uint32_t ah[2][4], al[2][4], bw[4][4];
            #pragma unroll
            for (int mt = 0; mt < 2; ++mt) {
                int r = m0 + mt * 16 + (L & 15);
                uint32_t off = r * 256 + ((cc ^ (r & 7)) << 4);
                ldsm4(ah[mt], sb + OF_XH + off);
                ldsm4(al[mt], sb + OF_XL + off);
            }
            #pragma unroll
            for (int np = 0; np < 4; ++np) {
                int rn = np * 16 + (L & 15);
                ldsm4(bw[np], sb + OF_W1H + rn * 256 + ((cc ^ (rn & 7)) << 4));
            }
            #pragma unroll
            for (int mt = 0; mt < 2; ++mt)
                #pragma unroll
                for (int np = 0; np < 4; ++np) {
                    hmma(acc[mt][2 * np],     ah[mt], bw[np][0], bw[np][2]);
                    hmma(acc[mt][2 * np + 1], ah[mt], bw[np][1], bw[np][3]);
                    hmma(acc[mt][2 * np],     al[mt], bw[np][0], bw[np][2]);
                    hmma(acc[mt][2 * np + 1], al[mt], bw[np][1], bw[np][3]);
                }
            #pragma unroll
            for (int np = 0; np < 4; ++np) {
                int rn = np * 16 + (L & 15);
                ldsm4(bw[np], sb + OF_W1L + rn * 256 + ((cc ^ (rn & 7)) << 4));
            }
            #pragma unroll
            for (int mt = 0; mt < 2; ++mt)
                #pragma unroll
                for (int np = 0; np < 4; ++np) {
                    hmma(acc[mt][2 * np],     ah[mt], bw[np][0], bw[np][2]);
                    hmma(acc[mt][2 * np + 1], ah[mt], bw[np][1], bw[np][3]);
                }
        }

        // ---- epilogue 1: relu(acc+b1) -> layer-2 A fragments (registers!) ----
        uint32_t a2h[2][4][4], a2l[2][4][4];
        #pragma unroll
        for (int mt = 0; mt < 2; ++mt)
            #pragma unroll
            for (int kt = 0; kt < 4; ++kt)
                #pragma unroll
                for (int hf = 0; hf < 2; ++hf) {
                    const int nt = 2 * kt + hf;
                    const float* d = acc[mt][nt];
                    const int c0 = nt * 8 + (L & 3) * 2;
                    float2 bb = *(float2*)(b1s + c0);
                    float h0 = fmaxf(d[0] + bb.x, 0.f), h1 = fmaxf(d[1] + bb.y, 0.f);
                    float h2 = fmaxf(d[2] + bb.x, 0.f), h3 = fmaxf(d[3] + bb.y, 0.f);
                    a2l[mt][kt][2 * hf]     = cvt_hilo(h0, h1, a2h[mt][kt][2 * hf]);
                    a2l[mt][kt][2 * hf + 1] = cvt_hilo(h2, h3, a2h[mt][kt][2 * hf + 1]);
                }

        // ---- layer 2 + gate + scatter, 4 chunks of (32 gate + 32 value) cols ----
        #pragma unroll 1
        for (int ch = 0; ch < 4; ++ch) {
            float aG[2][4][4], aV[2][4][4];
            #pragma unroll
            for (int mt = 0; mt < 2; ++mt)
                #pragma unroll
                for (int nt = 0; nt < 4; ++nt)
                    #pragma unroll
                    for (int j = 0; j < 4; ++j) { aG[mt][nt][j] = 0.f; aV[mt][nt][j] = 0.f; }

            #pragma unroll
            for (int ks = 0; ks < 4; ++ks) {
                const int cc = ks * 2 + (L >> 4);
                uint32_t bg[2][4], bv[2][4];
                #pragma unroll
                for (int np = 0; np < 2; ++np) {
                    int rg = 32 * ch + np * 16 + (L & 15);
                    int rv = 128 + 32 * ch + np * 16 + (L & 15);
                    ldsm4(bg[np], sb + OF_W2H + rg * 128 + ((cc ^ (rg & 7)) << 4));
                    ldsm4(bv[np], sb + OF_W2H + rv * 128 + ((cc ^ (rv & 7)) << 4));
                }
                #pragma unroll
                for (int mt = 0; mt < 2; ++mt)
                    #pragma unroll
                    for (int np = 0; np < 2; ++np) {
                        hmma(aG[mt][2 * np],     a2h[mt][ks], bg[np][0], bg[np][2]);
                        hmma(aG[mt][2 * np + 1], a2h[mt][ks], bg[np][1], bg[np][3]);
                        hmma(aV[mt][2 * np],     a2h[mt][ks], bv[np][0], bv[np][2]);
                        hmma(aV[mt][2 * np + 1], a2h[mt][ks], bv[np][1], bv[np][3]);
                        hmma(aG[mt][2 * np],     a2l[mt][ks], bg[np][0], bg[np][2]);
                        hmma(aG[mt][2 * np + 1], a2l[mt][ks], bg[np][1], bg[np][3]);
                        hmma(aV[mt][2 * np],     a2l[mt][ks], bv[np][0], bv[np][2]);
                        hmma(aV[mt][2 * np + 1], a2l[mt][ks], bv[np][1], bv[np][3]);
                    }
                #pragma unroll
                for (int np = 0; np < 2; ++np) {
                    int rg = 32 * ch + np * 16 + (L & 15);
                    int rv = 128 + 32 * ch + np * 16 + (L & 15);
                    ldsm4(bg[np], sb + OF_W2L + rg * 128 + ((cc ^ (rg & 7)) << 4));
                    ldsm4(bv[np], sb + OF_W2L + rv * 128 + ((cc ^ (rv & 7)) << 4));
                }
                #pragma unroll
                for (int mt = 0; mt < 2; ++mt)
                    #pragma unroll
                    for (int np = 0; np < 2; ++np) {
                        hmma(aG[mt][2 * np],     a2h[mt][ks], bg[np][0], bg[np][2]);
                        hmma(aG[mt][2 * np + 1], a2h[mt][ks], bg[np][1], bg[np][3]);
                        hmma(aV[mt][2 * np],     a2h[mt][ks], bv[np][0], bv[np][2]);
                        hmma(aV[mt][2 * np + 1], a2h[mt][ks], bv[np][1], bv[np][3]);
                    }
            }

            // epilogue: gated = v * sigmoid(g) -> red.v2
            #pragma unroll
            for (int mt = 0; mt < 2; ++mt) {
                const int r1 = m0 + mt * 16 + (L >> 2);
                const int gi1 = sGI[r1], gi2 = sGI[r1 + 8];
                #pragma unroll
                for (int nt = 0; nt < 4; ++nt) {
                    const int cg = 32 * ch + nt * 8 + (L & 3) * 2;
                    float2 bgc = *(float2*)(b2s + cg);
                    float2 bvc = *(float2*)(b2s + 128 + cg);
                    {
                        float g0 = aG[mt][nt][0] + bgc.x, g1 = aG[mt][nt][1] + bgc.y;
                        float v0 = aV[mt][nt][0] + bvc.x, v1 = aV[mt][nt][1] + bvc.y;
                        if (gi1 >= 0)
                            red2(g_graph_states + (size_t)gi1 * GS + cg,
                                 __fdividef(v0, 1.f + __expf(-g0)),
                                 __fdividef(v1, 1.f + __expf(-g1)));
                    }
                    {
                        float g0 = aG[mt][nt][2] + bgc.x, g1 = aG[mt][nt][3] + bgc.y;
                        float v0 = aV[mt][nt][2] + bvc.x, v1 = aV[mt][nt][3] + bvc.y;
                        if (gi2 >= 0)
                            red2(g_graph_states + (size_t)gi2 * GS + cg,
                                 __fdividef(v0, 1.f + __expf(-g0)),
                                 __fdividef(v1, 1.f + __expf(-g1)));
                    }
                }
            }
        }
        __syncthreads();
    }
}

// ---------------- MLP2 + re-zero accumulator ----------------
__global__ __launch_bounds__(128) void mlp2_rezero_kernel(
    const float* __restrict__ W3, const float* __restrict__ b3,
    const float* __restrict__ W4, const float* __restrict__ b4,
    float* __restrict__ out)
{
    __shared__ float W3s[GS * 32];
    __shared__ float W4s[32 * 16];
    __shared__ float b3s[32];
    __shared__ float b4s[16];

    const int tid = threadIdx.x;
    for (int i = tid; i < (GS * 32) / 4; i += 128) ((float4*)W3s)[i] = ((const float4*)W3)[i];
    for (int i = tid; i < (32 * 16) / 4; i += 128) ((float4*)W4s)[i] = ((const float4*)W4)[i];
    if (tid < 32) b3s[tid] = b3[tid];
    if (tid < 16) b4s[tid] = b4[tid];
    __syncthreads();

    const int g = blockIdx.x * 128 + tid;

    float h3[32];
    #pragma unroll
    for (int j = 0; j < 32; ++j) h3[j] = b3s[j];

    float4* gr = (float4*)(g_graph_states + (size_t)g * GS);
    #pragma unroll 1
    for (int k4 = 0; k4 < GS / 4; ++k4) {
        const float4 gv = gr[k4];
        #pragma unroll
        for (int kk = 0; kk < 4; ++kk) {
            const float gk = (kk == 0) ? gv.x : (kk == 1) ? gv.y : (kk == 2) ? gv.z : gv.w;
            const float* w = &W3s[(k4 * 4 + kk) * 32];
            #pragma unroll
            for (int j = 0; j < 32; ++j) h3[j] += gk * w[j];
        }
    }
    #pragma unroll
    for (int k4 = 0; k4 < GS / 4; ++k4) gr[k4] = make_float4(0.f, 0.f, 0.f, 0.f);

    float o[16];
    #pragma unroll
    for (int j = 0; j < 16; ++j) o[j] = b4s[j];
    #pragma unroll
    for (int k = 0; k < 32; ++k) {
        const float hk = fmaxf(h3[k], 0.f);
        #pragma unroll
        for (int j = 0; j < 16; ++j) o[j] += hk * W4s[k * 16 + j];
    }

    float4* op = (float4*)(out + (size_t)g * 16);
    op[0] = make_float4(o[0],  o[1],  o[2],  o[3]);
    op[1] = make_float4(o[4],  o[5],  o[6],  o[7]);
    op[2] = make_float4(o[8],  o[9],  o[10], o[11]);
    op[3] = make_float4(o[12], o[13], o[14], o[15]);
}

extern "C" void kernel_launch(void* const* d_in, const int* in_sizes, int n_in,
                              void* d_out, int out_size)
{
    const float* X  = (const float*)d_in[0];
    const int*   gi = (const int*)  d_in[1];
    const float* W1 = (const float*)d_in[2];
    const float* b1 = (const float*)d_in[3];
    const float* W2 = (const float*)d_in[4];
    const float* b2 = (const float*)d_in[5];
    const float* W3 = (const float*)d_in[6];
    const float* b3 = (const float*)d_in[7];
    const float* W4 = (const float*)d_in[8];
    const float* b4 = (const float*)d_in[9];
    float* out = (float*)d_out;

    cudaFuncSetAttribute(mma_fused_kernel,
                         cudaFuncAttributeMaxDynamicSharedMemorySize, SMEM_TOTAL);

    prep_kernel<<<64, 256>>>(W1, W2);
    // g_graph_states: zero-initialized at load; re-zeroed by mlp2_rezero each call.
    mma_fused_kernel<<<148, 128, SMEM_TOTAL>>>(X, gi, b1, b2,    0, 3907);
    mma_fused_kernel<<<148, 128, SMEM_TOTAL>>>(X, gi, b1, b2, 3907, N_TILES);
    mlp2_rezero_kernel<<<NG / 128, 128>>>(W3, b3, W4, b4, out);
}

// round 9
// speedup vs baseline: 3.8967x; 1.3733x over previous
#include <cuda_runtime.h>
#include <cuda_bf16.h>
#include <cstdint>

#define N_NODES 1000000
#define D_IN    128
#define H1      64
#define D2C     256
#define GS      128
#define NG      4096
#define TILE_M  256
#define N_TILES ((N_NODES + TILE_M - 1) / TILE_M)   // 3907

__device__ float g_graph_states[NG * GS];
__device__ __align__(16) __nv_bfloat16 gW1h[H1 * D_IN];    // [n][k]
__device__ __align__(16) __nv_bfloat16 gW1l[H1 * D_IN];
__device__ __align__(16) __nv_bfloat16 gW2h[D2C * H1];     // [n][k]
__device__ __align__(16) __nv_bfloat16 gW2l[D2C * H1];

// ---------------- helpers ----------------
__device__ __forceinline__ uint32_t smem_u32(const void* p) {
    uint32_t a;
    asm("{ .reg .u64 t; cvta.to.shared.u64 t, %1; cvt.u32.u64 %0, t; }" : "=r"(a) : "l"(p));
    return a;
}
__device__ __forceinline__ void ldsm4(uint32_t* r, uint32_t addr) {
    asm volatile("ldmatrix.sync.aligned.m8n8.x4.shared.b16 {%0,%1,%2,%3}, [%4];"
                 : "=r"(r[0]), "=r"(r[1]), "=r"(r[2]), "=r"(r[3]) : "r"(addr));
}
__device__ __forceinline__ void hmma(float* d, const uint32_t* a, uint32_t b0, uint32_t b1) {
    asm volatile("mma.sync.aligned.m16n8k16.row.col.f32.bf16.bf16.f32 "
                 "{%0,%1,%2,%3}, {%4,%5,%6,%7}, {%8,%9}, {%0,%1,%2,%3};"
                 : "+f"(d[0]), "+f"(d[1]), "+f"(d[2]), "+f"(d[3])
                 : "r"(a[0]), "r"(a[1]), "r"(a[2]), "r"(a[3]), "r"(b0), "r"(b1));
}
__device__ __forceinline__ uint32_t cvt_hi(float f0, float f1) {
    uint32_t r;
    asm("cvt.rn.bf16x2.f32 %0, %1, %2;" : "=r"(r) : "f"(f1), "f"(f0));
    return r;
}
__device__ __forceinline__ uint32_t cvt_hilo(float f0, float f1, uint32_t& hi) {
    hi = cvt_hi(f0, f1);
    float h0 = __uint_as_float(hi << 16);
    float h1 = __uint_as_float(hi & 0xffff0000u);
    return cvt_hi(f0 - h0, f1 - h1);
}
__device__ __forceinline__ void red2(float* p, float x, float y) {
    asm volatile("red.global.add.v2.f32 [%0], {%1,%2};" :: "l"(p), "f"(x), "f"(y) : "memory");
}

// ---------------- prep: W transpose + hi/lo split ----------------
__global__ void prep_kernel(const float* __restrict__ W1, const float* __restrict__ W2) {
    int i = blockIdx.x * blockDim.x + threadIdx.x;
    if (i < H1 * D_IN) {
        int n = i >> 7, k = i & 127;
        float w = W1[k * H1 + n];
        __nv_bfloat16 h = __float2bfloat16(w);
        gW1h[i] = h;
        gW1l[i] = __float2bfloat16(w - __bfloat162float(h));
    }
    if (i < D2C * H1) {
        int n = i >> 6, k = i & 63;
        float w = W2[k * D2C + n];
        __nv_bfloat16 h = __float2bfloat16(w);
        gW2h[i] = h;
        gW2l[i] = __float2bfloat16(w - __bfloat162float(h));
    }
}

// ---------------- SMEM layout (bytes) ----------------
#define OF_XH  0          // 256 rows x 256B (swizzled, 16 chunks)
#define OF_XL  65536
#define OF_W1H 131072     // 64 rows x 256B
#define OF_W1L 147456
#define OF_W2H 163840     // 256 rows x 128B (8 chunks)
#define OF_W2L 196608
#define OF_B1  229376     // 64 f32
#define OF_B2  229632     // 256 f32
#define OF_GI  230656     // 256 int
#define SMEM_TOTAL 231680

// ---------------- fused HMMA kernel: 256 threads, TILE_M=256 ----------------
__global__ __launch_bounds__(256, 1)
void mma_fused_kernel(const float* __restrict__ X, const int* __restrict__ gidx,
                      const float* __restrict__ b1, const float* __restrict__ b2,
                      int tile_begin, int tile_end)
{
    extern __shared__ char smem[];
    const uint32_t sb = smem_u32(smem);
    const int tid = threadIdx.x;
    const int L   = tid & 31;
    const int m0  = (tid >> 5) * 32;            // warp's 32 rows (8 warps x 32 = 256)
    float* b1s = (float*)(smem + OF_B1);
    float* b2s = (float*)(smem + OF_B2);
    int*   sGI = (int*)(smem + OF_GI);

    // ---- stage weights (swizzled for ldmatrix) + biases ----
    for (int i = tid; i < H1 * 16; i += 256) {            // W1: 64 rows x 16 chunks
        int n = i >> 4, c = i & 15;
        uint32_t off = n * 256 + ((c ^ (n & 7)) << 4);
        *(uint4*)(smem + OF_W1H + off) = *(const uint4*)(gW1h + n * D_IN + c * 8);
        *(uint4*)(smem + OF_W1L + off) = *(const uint4*)(gW1l + n * D_IN + c * 8);
    }
    for (int i = tid; i < D2C * 8; i += 256) {            // W2: 256 rows x 8 chunks
        int n = i >> 3, c = i & 7;
        uint32_t off = n * 128 + ((c ^ (n & 7)) << 4);
        *(uint4*)(smem + OF_W2H + off) = *(const uint4*)(gW2h + n * H1 + c * 8);
        *(uint4*)(smem + OF_W2L + off) = *(const uint4*)(gW2l + n * H1 + c * 8);
    }
    if (tid < 64) b1s[tid] = b1[tid];
    if (tid < 256) b2s[tid] = b2[tid];
    __syncthreads();

    for (int tile = tile_begin + blockIdx.x; tile < tile_end; tile += gridDim.x) {
        // ---- phase A: X row (1 per thread) -> hi/lo bf16 swizzled SMEM ----
        const int node = tile * TILE_M + tid;
        const bool valid = node < N_NODES;
        sGI[tid] = valid ? __ldg(&gidx[node]) : -1;
        const float4* xr = (const float4*)(X + (size_t)node * D_IN);
        #pragma unroll 4
        for (int c = 0; c < 16; ++c) {
            uint4 H = make_uint4(0, 0, 0, 0), Lo = make_uint4(0, 0, 0, 0);
            if (valid) {
                float4 a = __ldg(&xr[2 * c]), b = __ldg(&xr[2 * c + 1]);
                Lo.x = cvt_hilo(a.x, a.y, H.x);
                Lo.y = cvt_hilo(a.z, a.w, H.y);
                Lo.z = cvt_hilo(b.x, b.y, H.z);
                Lo.w = cvt_hilo(b.z, b.w, H.w);
            }
            uint32_t off = tid * 256 + ((c ^ (tid & 7)) << 4);
            *(uint4*)(smem + OF_XH + off) = H;
            *(uint4*)(smem + OF_XL + off) = Lo;
        }
        __syncthreads();

        // ---- layer 1: warp's [32,128] @ W1^T[128,64], 3 split products ----
        float acc[2][8][4];
        #pragma unroll
        for (int mt = 0; mt < 2; ++mt)
            #pragma unroll
            for (int nt = 0; nt < 8; ++nt)
                #pragma unroll
                for (int j = 0; j < 4; ++j) acc[mt][nt][j] = 0.f;

        #pragma unroll 1
        for (int ks = 0; ks < 8; ++ks) {
            const int cc = ks * 2 + (L >> 4);
            uint32_t ah[2][4], al[2][4], bw[4][4];
            #pragma unroll
            for (int mt = 0; mt < 2; ++mt) {
                int r = m0 + mt * 16 + (L & 15);
                uint32_t off = r * 256 + ((cc ^ (r & 7)) << 4);
                ldsm4(ah[mt], sb + OF_XH + off);
                ldsm4(al[mt], sb + OF_XL + off);
            }
            #pragma unroll
            for (int np = 0; np < 4; ++np) {
                int rn = np * 16 + (L & 15);
                ldsm4(bw[np], sb + OF_W1H + rn * 256 + ((cc ^ (rn & 7)) << 4));
            }
            #pragma unroll
            for (int mt = 0; mt < 2; ++mt)
                #pragma unroll
                for (int np = 0; np < 4; ++np) {
                    hmma(acc[mt][2 * np],     ah[mt], bw[np][0], bw[np][2]);
                    hmma(acc[mt][2 * np + 1], ah[mt], bw[np][1], bw[np][3]);
                    hmma(acc[mt][2 * np],     al[mt], bw[np][0], bw[np][2]);
                    hmma(acc[mt][2 * np + 1], al[mt], bw[np][1], bw[np][3]);
                }
            #pragma unroll
            for (int np = 0; np < 4; ++np) {
                int rn = np * 16 + (L & 15);
                ldsm4(bw[np], sb + OF_W1L + rn * 256 + ((cc ^ (rn & 7)) << 4));
            }
            #pragma unroll
            for (int mt = 0; mt < 2; ++mt)
                #pragma unroll
                for (int np = 0; np < 4; ++np) {
                    hmma(acc[mt][2 * np],     ah[mt], bw[np][0], bw[np][2]);
                    hmma(acc[mt][2 * np + 1], ah[mt], bw[np][1], bw[np][3]);
                }
        }

        // ---- epilogue 1: relu(acc+b1) -> layer-2 A fragments (registers) ----
        uint32_t a2h[2][4][4], a2l[2][4][4];
        #pragma unroll
        for (int mt = 0; mt < 2; ++mt)
            #pragma unroll
            for (int kt = 0; kt < 4; ++kt)
                #pragma unroll
                for (int hf = 0; hf < 2; ++hf) {
                    const int nt = 2 * kt + hf;
                    const float* d = acc[mt][nt];
                    const int c0 = nt * 8 + (L & 3) * 2;
                    float2 bb = *(float2*)(b1s + c0);
                    float h0 = fmaxf(d[0] + bb.x, 0.f), h1 = fmaxf(d[1] + bb.y, 0.f);
                    float h2 = fmaxf(d[2] + bb.x, 0.f), h3 = fmaxf(d[3] + bb.y, 0.f);
                    a2l[mt][kt][2 * hf]     = cvt_hilo(h0, h1, a2h[mt][kt][2 * hf]);
                    a2l[mt][kt][2 * hf + 1] = cvt_hilo(h2, h3, a2h[mt][kt][2 * hf + 1]);
                }

        // ---- layer 2 + gate + scatter, 4 chunks of (32 gate + 32 value) cols ----
        #pragma unroll 1
        for (int ch = 0; ch < 4; ++ch) {
            float aG[2][4][4], aV[2][4][4];
            #pragma unroll
            for (int mt = 0; mt < 2; ++mt)
                #pragma unroll
                for (int nt = 0; nt < 4; ++nt)
                    #pragma unroll
                    for (int j = 0; j < 4; ++j) { aG[mt][nt][j] = 0.f; aV[mt][nt][j] = 0.f; }

            #pragma unroll
            for (int ks = 0; ks < 4; ++ks) {
                const int cc = ks * 2 + (L >> 4);
                uint32_t bg[2][4], bv[2][4];
                #pragma unroll
                for (int np = 0; np < 2; ++np) {
                    int rg = 32 * ch + np * 16 + (L & 15);
                    int rv = 128 + 32 * ch + np * 16 + (L & 15);
                    ldsm4(bg[np], sb + OF_W2H + rg * 128 + ((cc ^ (rg & 7)) << 4));
                    ldsm4(bv[np], sb + OF_W2H + rv * 128 + ((cc ^ (rv & 7)) << 4));
                }
                #pragma unroll
                for (int mt = 0; mt < 2; ++mt)
                    #pragma unroll
                    for (int np = 0; np < 2; ++np) {
                        hmma(aG[mt][2 * np],     a2h[mt][ks], bg[np][0], bg[np][2]);
                        hmma(aG[mt][2 * np + 1], a2h[mt][ks], bg[np][1], bg[np][3]);
                        hmma(aV[mt][2 * np],     a2h[mt][ks], bv[np][0], bv[np][2]);
                        hmma(aV[mt][2 * np + 1], a2h[mt][ks], bv[np][1], bv[np][3]);
                        hmma(aG[mt][2 * np],     a2l[mt][ks], bg[np][0], bg[np][2]);
                        hmma(aG[mt][2 * np + 1], a2l[mt][ks], bg[np][1], bg[np][3]);
                        hmma(aV[mt][2 * np],     a2l[mt][ks], bv[np][0], bv[np][2]);
                        hmma(aV[mt][2 * np + 1], a2l[mt][ks], bv[np][1], bv[np][3]);
                    }
                #pragma unroll
                for (int np = 0; np < 2; ++np) {
                    int rg = 32 * ch + np * 16 + (L & 15);
                    int rv = 128 + 32 * ch + np * 16 + (L & 15);
                    ldsm4(bg[np], sb + OF_W2L + rg * 128 + ((cc ^ (rg & 7)) << 4));
                    ldsm4(bv[np], sb + OF_W2L + rv * 128 + ((cc ^ (rv & 7)) << 4));
                }
                #pragma unroll
                for (int mt = 0; mt < 2; ++mt)
                    #pragma unroll
                    for (int np = 0; np < 2; ++np) {
                        hmma(aG[mt][2 * np],     a2h[mt][ks], bg[np][0], bg[np][2]);
                        hmma(aG[mt][2 * np + 1], a2h[mt][ks], bg[np][1], bg[np][3]);
                        hmma(aV[mt][2 * np],     a2h[mt][ks], bv[np][0], bv[np][2]);
                        hmma(aV[mt][2 * np + 1], a2h[mt][ks], bv[np][1], bv[np][3]);
                    }
            }

            // epilogue: gated = v * sigmoid(g) -> red.v2
            #pragma unroll
            for (int mt = 0; mt < 2; ++mt) {
                const int r1 = m0 + mt * 16 + (L >> 2);
                const int gi1 = sGI[r1], gi2 = sGI[r1 + 8];
                #pragma unroll
                for (int nt = 0; nt < 4; ++nt) {
                    const int cg = 32 * ch + nt * 8 + (L & 3) * 2;
                    float2 bgc = *(float2*)(b2s + cg);
                    float2 bvc = *(float2*)(b2s + 128 + cg);
                    {
                        float g0 = aG[mt][nt][0] + bgc.x, g1 = aG[mt][nt][1] + bgc.y;
                        float v0 = aV[mt][nt][0] + bvc.x, v1 = aV[mt][nt][1] + bvc.y;
                        if (gi1 >= 0)
                            red2(g_graph_states + (size_t)gi1 * GS + cg,
                                 __fdividef(v0, 1.f + __expf(-g0)),
                                 __fdividef(v1, 1.f + __expf(-g1)));
                    }
                    {
                        float g0 = aG[mt][nt][2] + bgc.x, g1 = aG[mt][nt][3] + bgc.y;
                        float v0 = aV[mt][nt][2] + bvc.x, v1 = aV[mt][nt][3] + bvc.y;
                        if (gi2 >= 0)
                            red2(g_graph_states + (size_t)gi2 * GS + cg,
                                 __fdividef(v0, 1.f + __expf(-g0)),
                                 __fdividef(v1, 1.f + __expf(-g1)));
                    }
                }
            }
        }
        __syncthreads();
    }
}

// ---------------- MLP2 + re-zero accumulator ----------------
__global__ __launch_bounds__(128) void mlp2_rezero_kernel(
    const float* __restrict__ W3, const float* __restrict__ b3,
    const float* __restrict__ W4, const float* __restrict__ b4,
    float* __restrict__ out)
{
    __shared__ float W3s[GS * 32];
    __shared__ float W4s[32 * 16];
    __shared__ float b3s[32];
    __shared__ float b4s[16];

    const int tid = threadIdx.x;
    for (int i = tid; i < (GS * 32) / 4; i += 128) ((float4*)W3s)[i] = ((const float4*)W3)[i];
    for (int i = tid; i < (32 * 16) / 4; i += 128) ((float4*)W4s)[i] = ((const float4*)W4)[i];
    if (tid < 32) b3s[tid] = b3[tid];
    if (tid < 16) b4s[tid] = b4[tid];
    __syncthreads();

    const int g = blockIdx.x * 128 + tid;

    float h3[32];
    #pragma unroll
    for (int j = 0; j < 32; ++j) h3[j] = b3s[j];

    float4* gr = (float4*)(g_graph_states + (size_t)g * GS);
    #pragma unroll 1
    for (int k4 = 0; k4 < GS / 4; ++k4) {
        const float4 gv = gr[k4];
        #pragma unroll
        for (int kk = 0; kk < 4; ++kk) {
            const float gk = (kk == 0) ? gv.x : (kk == 1) ? gv.y : (kk == 2) ? gv.z : gv.w;
            const float* w = &W3s[(k4 * 4 + kk) * 32];
            #pragma unroll
            for (int j = 0; j < 32; ++j) h3[j] += gk * w[j];
        }
    }
    #pragma unroll
    for (int k4 = 0; k4 < GS / 4; ++k4) gr[k4] = make_float4(0.f, 0.f, 0.f, 0.f);

    float o[16];
    #pragma unroll
    for (int j = 0; j < 16; ++j) o[j] = b4s[j];
    #pragma unroll
    for (int k = 0; k < 32; ++k) {
        const float hk = fmaxf(h3[k], 0.f);
        #pragma unroll
        for (int j = 0; j < 16; ++j) o[j] += hk * W4s[k * 16 + j];
    }

    float4* op = (float4*)(out + (size_t)g * 16);
    op[0] = make_float4(o[0],  o[1],  o[2],  o[3]);
    op[1] = make_float4(o[4],  o[5],  o[6],  o[7]);
    op[2] = make_float4(o[8],  o[9],  o[10], o[11]);
    op[3] = make_float4(o[12], o[13], o[14], o[15]);
}

extern "C" void kernel_launch(void* const* d_in, const int* in_sizes, int n_in,
                              void* d_out, int out_size)
{
    const float* X  = (const float*)d_in[0];
    const int*   gi = (const int*)  d_in[1];
    const float* W1 = (const float*)d_in[2];
    const float* b1 = (const float*)d_in[3];
    const float* W2 = (const float*)d_in[4];
    const float* b2 = (const float*)d_in[5];
    const float* W3 = (const float*)d_in[6];
    const float* b3 = (const float*)d_in[7];
    const float* W4 = (const float*)d_in[8];
    const float* b4 = (const float*)d_in[9];
    float* out = (float*)d_out;

    cudaFuncSetAttribute(mma_fused_kernel,
                         cudaFuncAttributeMaxDynamicSharedMemorySize, SMEM_TOTAL);

    prep_kernel<<<64, 256>>>(W1, W2);
    // g_graph_states: zero-initialized at load; re-zeroed by mlp2_rezero each call.
    mma_fused_kernel<<<148, 256, SMEM_TOTAL>>>(X, gi, b1, b2,    0, 1954);
    mma_fused_kernel<<<148, 256, SMEM_TOTAL>>>(X, gi, b1, b2, 1954, N_TILES);
    mlp2_rezero_kernel<<<NG / 128, 128>>>(W3, b3, W4, b4, out);
}